// round 1
// baseline (speedup 1.0000x reference)
#include <cuda_runtime.h>
#include <cstdint>

#define T_FRAMES 16384
#define E_DIM    1024
#define M_MODELS 8
#define K_CLUST  512

#define TM  128   // frames per tile
#define TN  64    // centroids per tile
#define TKC 32    // K-chunk
#define MAXT 128  // max m-tiles per model = T/TM
#define APAD 130
#define BPAD 65

// ---- persistent scratch (no allocation allowed) ----
__device__ unsigned long long g_packed[T_FRAMES];
__device__ int   g_counts[M_MODELS];
__device__ int   g_rows[M_MODELS * T_FRAMES];
__device__ float g_chalf[M_MODELS * K_CLUST];

// ---------------- helpers ----------------
__device__ __forceinline__ unsigned long long pack2(float lo, float hi) {
    unsigned long long r;
    asm("mov.b64 %0, {%1, %2};" : "=l"(r)
        : "r"(__float_as_uint(lo)), "r"(__float_as_uint(hi)));
    return r;
}
__device__ __forceinline__ void fma2(unsigned long long& acc,
                                     unsigned long long a, unsigned long long b) {
    asm("fma.rn.f32x2 %0, %1, %2, %0;" : "+l"(acc) : "l"(a), "l"(b));
}
__device__ __forceinline__ unsigned int fkey(float f) {
    unsigned u = __float_as_uint(f);
    return (u & 0x80000000u) ? ~u : (u | 0x80000000u);
}

// ---------------- prep kernels ----------------
__global__ void init_kernel() {
    int t = blockIdx.x * blockDim.x + threadIdx.x;
    if (t < T_FRAMES) g_packed[t] = 0xFFFFFFFFFFFFFFFFull;
    if (t < M_MODELS) g_counts[t] = 0;
}

__global__ void bucket_kernel(const int* __restrict__ model_idx) {
    int t = blockIdx.x * blockDim.x + threadIdx.x;
    if (t >= T_FRAMES) return;
    int m = model_idx[t];
    int pos = atomicAdd(&g_counts[m], 1);
    g_rows[m * T_FRAMES + pos] = t;
}

__global__ void chalf_kernel(const float* __restrict__ centroids) {
    int warp = (blockIdx.x * blockDim.x + threadIdx.x) >> 5;
    int lane = threadIdx.x & 31;
    if (warp >= M_MODELS * K_CLUST) return;
    const float4* p = reinterpret_cast<const float4*>(centroids + (size_t)warp * E_DIM);
    float s = 0.f;
    #pragma unroll
    for (int q = 0; q < 8; ++q) {
        float4 v = p[lane + 32 * q];
        s += v.x * v.x + v.y * v.y + v.z * v.z + v.w * v.w;
    }
    #pragma unroll
    for (int o = 16; o; o >>= 1) s += __shfl_xor_sync(0xffffffffu, s, o);
    if (lane == 0) g_chalf[warp] = 0.5f * s;
}

// ---------------- grouped GEMM + fused argmin ----------------
// grid.x = M_MODELS * MAXT (model = bx>>7, mtile = bx&127), grid.y = K_CLUST/TN
__global__ __launch_bounds__(256, 2)
void gemm_argmin_kernel(const float* __restrict__ emb, const float* __restrict__ cent) {
    __shared__ float As[TKC][APAD];   // k-major: As[kk][row]
    __shared__ float Bs[TKC][BPAD];   // k-major: Bs[kk][col]

    const int m   = blockIdx.x >> 7;
    const int mt  = blockIdx.x & 127;
    const int cnt = g_counts[m];
    if (mt * TM >= cnt) return;
    const int nt = blockIdx.y;
    const int* rowsm = g_rows + m * T_FRAMES;

    const int tid = threadIdx.x;
    const int tx  = tid & 15;   // 4 centroid cols: 4*tx + jc
    const int ty  = tid >> 4;   // 8 frame rows: 2*ty + {0,1} + 32*i

    // A gmem load plan: 128 rows x 8 float4 = 1024 float4, 4 per thread
    const float* aptr[4]; int arow[4];
    #pragma unroll
    for (int j = 0; j < 4; ++j) {
        int f = tid + 256 * j;
        arow[j] = f >> 3;
        int akq = f & 7;
        int gr = mt * TM + arow[j];
        int frame = rowsm[min(gr, cnt - 1)];
        aptr[j] = emb + (size_t)frame * E_DIM + akq * 4;
    }
    int akqv[4];
    #pragma unroll
    for (int j = 0; j < 4; ++j) akqv[j] = (tid + 256 * j) & 7;

    // B gmem load plan: 64 cols x 8 float4 = 512 float4, 2 per thread
    const float* bptr[2]; int bcol[2], bkq[2];
    #pragma unroll
    for (int j = 0; j < 2; ++j) {
        int f = tid + 256 * j;
        bcol[j] = f >> 3;
        bkq[j]  = f & 7;
        bptr[j] = cent + (size_t)(m * K_CLUST + nt * TN + bcol[j]) * E_DIM + bkq[j] * 4;
    }

    unsigned long long acc[4][4];
    #pragma unroll
    for (int i = 0; i < 4; ++i)
        #pragma unroll
        for (int jc = 0; jc < 4; ++jc) acc[i][jc] = 0ull;

    float4 va[4], vb[2];
    #pragma unroll
    for (int j = 0; j < 4; ++j) va[j] = *reinterpret_cast<const float4*>(aptr[j]);
    #pragma unroll
    for (int j = 0; j < 2; ++j) vb[j] = *reinterpret_cast<const float4*>(bptr[j]);

    const int NKB = E_DIM / TKC;  // 32
    for (int kb = 0; kb < NKB; ++kb) {
        __syncthreads();
        #pragma unroll
        for (int j = 0; j < 4; ++j) {
            As[4 * akqv[j] + 0][arow[j]] = va[j].x;
            As[4 * akqv[j] + 1][arow[j]] = va[j].y;
            As[4 * akqv[j] + 2][arow[j]] = va[j].z;
            As[4 * akqv[j] + 3][arow[j]] = va[j].w;
        }
        #pragma unroll
        for (int j = 0; j < 2; ++j) {
            Bs[4 * bkq[j] + 0][bcol[j]] = vb[j].x;
            Bs[4 * bkq[j] + 1][bcol[j]] = vb[j].y;
            Bs[4 * bkq[j] + 2][bcol[j]] = vb[j].z;
            Bs[4 * bkq[j] + 3][bcol[j]] = vb[j].w;
        }
        __syncthreads();
        if (kb + 1 < NKB) {   // prefetch next chunk into regs, overlaps compute
            #pragma unroll
            for (int j = 0; j < 4; ++j)
                va[j] = *reinterpret_cast<const float4*>(aptr[j] + (kb + 1) * TKC);
            #pragma unroll
            for (int j = 0; j < 2; ++j)
                vb[j] = *reinterpret_cast<const float4*>(bptr[j] + (kb + 1) * TKC);
        }
        #pragma unroll 8
        for (int kk = 0; kk < TKC; ++kk) {
            unsigned long long a0 = *reinterpret_cast<const unsigned long long*>(&As[kk][2 * ty]);
            unsigned long long a1 = *reinterpret_cast<const unsigned long long*>(&As[kk][2 * ty + 32]);
            unsigned long long a2 = *reinterpret_cast<const unsigned long long*>(&As[kk][2 * ty + 64]);
            unsigned long long a3 = *reinterpret_cast<const unsigned long long*>(&As[kk][2 * ty + 96]);
            unsigned long long bd[4];
            #pragma unroll
            for (int jc = 0; jc < 4; ++jc) {
                float b = Bs[kk][4 * tx + jc];
                bd[jc] = pack2(b, b);
            }
            #pragma unroll
            for (int jc = 0; jc < 4; ++jc) {
                fma2(acc[0][jc], a0, bd[jc]);
                fma2(acc[1][jc], a1, bd[jc]);
                fma2(acc[2][jc], a2, bd[jc]);
                fma2(acc[3][jc], a3, bd[jc]);
            }
        }
    }

    // ---- epilogue: s = 0.5*c^2 - dot, per-row argmin, cross-tile atomicMin ----
    const float* chalfp = g_chalf + m * K_CLUST + nt * TN;
    float ch[4];
    #pragma unroll
    for (int jc = 0; jc < 4; ++jc) ch[jc] = chalfp[4 * tx + jc];

    #pragma unroll
    for (int i = 0; i < 4; ++i) {
        #pragma unroll
        for (int half = 0; half < 2; ++half) {
            float best; int bc;
            {
                unsigned long long a = acc[i][0];
                float dot = half ? __uint_as_float((unsigned)(a >> 32))
                                 : __uint_as_float((unsigned)a);
                best = ch[0] - dot;
                bc = nt * TN + 4 * tx;
            }
            #pragma unroll
            for (int jc = 1; jc < 4; ++jc) {
                unsigned long long a = acc[i][jc];
                float dot = half ? __uint_as_float((unsigned)(a >> 32))
                                 : __uint_as_float((unsigned)a);
                float s = ch[jc] - dot;
                if (s < best) { best = s; bc = nt * TN + 4 * tx + jc; }  // cols increasing: tie keeps first
            }
            // reduce across tx (lanes xor 1,2,4,8 stay within 16-lane half)
            #pragma unroll
            for (int o = 1; o < 16; o <<= 1) {
                float ov = __shfl_xor_sync(0xffffffffu, best, o);
                int   oc = __shfl_xor_sync(0xffffffffu, bc, o);
                if (ov < best || (ov == best && oc < bc)) { best = ov; bc = oc; }
            }
            if (tx == 0) {
                int row = 2 * ty + half + 32 * i;
                int gr = mt * TM + row;
                if (gr < cnt) {
                    int frame = rowsm[gr];
                    unsigned long long key =
                        ((unsigned long long)fkey(best) << 32) | (unsigned)bc;
                    atomicMin(&g_packed[frame], key);
                }
            }
        }
    }
}

// ---------------- output gather ----------------
__global__ void gather_kernel(const float* __restrict__ cent,
                              const int* __restrict__ model_idx,
                              float* __restrict__ out) {
    int idx = blockIdx.x * blockDim.x + threadIdx.x;  // float4 index
    if (idx >= T_FRAMES * (E_DIM / 4)) return;
    int t  = idx >> 8;        // 256 float4 per frame
    int e4 = idx & 255;
    int code = (int)(unsigned)(g_packed[t] & 0xFFFFFFFFull);
    size_t row = (size_t)(model_idx[t] * K_CLUST + code);
    reinterpret_cast<float4*>(out)[idx] =
        reinterpret_cast<const float4*>(cent)[row * 256 + e4];
}

// ---------------- launch ----------------
extern "C" void kernel_launch(void* const* d_in, const int* in_sizes, int n_in,
                              void* d_out, int out_size) {
    const float* emb  = (const float*)d_in[0];
    const float* cent = (const float*)d_in[1];
    const int*   midx = (const int*)d_in[2];
    float* out = (float*)d_out;

    init_kernel<<<(T_FRAMES + 255) / 256, 256>>>();
    bucket_kernel<<<(T_FRAMES + 255) / 256, 256>>>(midx);
    chalf_kernel<<<(M_MODELS * K_CLUST * 32 + 255) / 256, 256>>>(cent);

    dim3 grid(M_MODELS * MAXT, K_CLUST / TN);  // (1024, 8)
    gemm_argmin_kernel<<<grid, 256>>>(emb, cent);

    gather_kernel<<<(T_FRAMES * (E_DIM / 4) + 255) / 256, 256>>>(cent, midx, out);
}

// round 4
// speedup vs baseline: 2.4781x; 2.4781x over previous
#include <cuda_runtime.h>
#include <cuda_bf16.h>
#include <cstdint>

#define T_FRAMES 16384
#define E_DIM    1024
#define M_MODELS 8
#define K_CLUST  512

#define TM   128            // frames per CTA tile
#define TN   128            // centroids per CTA tile
#define KBLK 64             // bf16 elements per K stage (128B rows)
#define NSTAGE (E_DIM / KBLK)   // 16
#define MAXT (T_FRAMES / TM)    // 128
#define TAU  10.0f

// ---- persistent scratch (no allocation allowed) ----
__device__ __nv_bfloat16 g_emb_bf[T_FRAMES * E_DIM];               // 33.5MB
__device__ __nv_bfloat16 g_cent_bf[M_MODELS * K_CLUST * E_DIM];    // 8.4MB
__device__ float g_scores[T_FRAMES * K_CLUST];                     // 33.5MB
__device__ int   g_counts[M_MODELS];
__device__ int   g_rows[M_MODELS * T_FRAMES];
__device__ float g_chalf[M_MODELS * K_CLUST];
__device__ int   g_code[T_FRAMES];

// ================= helpers =================
__device__ __forceinline__ uint32_t smem_u32(const void* p) {
    uint32_t a;
    asm("{ .reg .u64 t; cvta.to.shared.u64 t, %1; cvt.u32.u64 %0, t; }" : "=r"(a) : "l"(p));
    return a;
}
__device__ __forceinline__ void cp16(uint32_t dst, const void* src) {
    asm volatile("cp.async.cg.shared.global [%0], [%1], 16;" :: "r"(dst), "l"(src));
}
__device__ __forceinline__ void cp_commit() {
    asm volatile("cp.async.commit_group;" ::: "memory");
}
__device__ __forceinline__ void ldmx4(uint32_t addr, uint32_t& r0, uint32_t& r1,
                                      uint32_t& r2, uint32_t& r3) {
    asm volatile("ldmatrix.sync.aligned.m8n8.x4.shared.b16 {%0,%1,%2,%3}, [%4];"
                 : "=r"(r0), "=r"(r1), "=r"(r2), "=r"(r3) : "r"(addr));
}
__device__ __forceinline__ void mma_bf16(float* c, uint32_t a0, uint32_t a1,
                                         uint32_t a2, uint32_t a3,
                                         uint32_t b0, uint32_t b1) {
    asm volatile(
        "mma.sync.aligned.m16n8k16.row.col.f32.bf16.bf16.f32 "
        "{%0,%1,%2,%3}, {%4,%5,%6,%7}, {%8,%9}, {%0,%1,%2,%3};"
        : "+f"(c[0]), "+f"(c[1]), "+f"(c[2]), "+f"(c[3])
        : "r"(a0), "r"(a1), "r"(a2), "r"(a3), "r"(b0), "r"(b1));
}

// ================= prep kernels =================
__global__ void init_kernel() {
    int t = threadIdx.x;
    if (t < M_MODELS) g_counts[t] = 0;
}

__global__ void bucket_kernel(const int* __restrict__ model_idx) {
    int t = blockIdx.x * blockDim.x + threadIdx.x;
    if (t >= T_FRAMES) return;
    int m = model_idx[t];
    int pos = atomicAdd(&g_counts[m], 1);
    g_rows[m * T_FRAMES + pos] = t;
}

__global__ void cvt_emb_kernel(const float* __restrict__ src) {
    int i = blockIdx.x * blockDim.x + threadIdx.x;
    if (i >= T_FRAMES * E_DIM / 4) return;
    float4 v = reinterpret_cast<const float4*>(src)[i];
    __nv_bfloat162* d = reinterpret_cast<__nv_bfloat162*>(g_emb_bf);
    d[2 * i]     = __floats2bfloat162_rn(v.x, v.y);
    d[2 * i + 1] = __floats2bfloat162_rn(v.z, v.w);
}

__global__ void cvt_cent_kernel(const float* __restrict__ src) {
    int i = blockIdx.x * blockDim.x + threadIdx.x;
    if (i >= M_MODELS * K_CLUST * E_DIM / 4) return;
    float4 v = reinterpret_cast<const float4*>(src)[i];
    __nv_bfloat162* d = reinterpret_cast<__nv_bfloat162*>(g_cent_bf);
    d[2 * i]     = __floats2bfloat162_rn(v.x, v.y);
    d[2 * i + 1] = __floats2bfloat162_rn(v.z, v.w);
}

__global__ void chalf_kernel(const float* __restrict__ centroids) {
    int warp = (blockIdx.x * blockDim.x + threadIdx.x) >> 5;
    int lane = threadIdx.x & 31;
    if (warp >= M_MODELS * K_CLUST) return;
    const float4* p = reinterpret_cast<const float4*>(centroids + (size_t)warp * E_DIM);
    float s = 0.f;
    #pragma unroll
    for (int q = 0; q < 8; ++q) {
        float4 v = p[lane + 32 * q];
        s += v.x * v.x + v.y * v.y + v.z * v.z + v.w * v.w;
    }
    #pragma unroll
    for (int o = 16; o; o >>= 1) s += __shfl_xor_sync(0xffffffffu, s, o);
    if (lane == 0) g_chalf[warp] = 0.5f * s;
}

// ================= approx GEMM: scores = 0.5*c^2 - x.c (bf16 mma.sync) =================
// smem layout (bytes): A[2][16KB] @0, B[2][16KB] @32768, rowidx @65536, chalf @66048
#define SM_B0     32768
#define SM_ROWIDX 65536
#define SM_CHALF  66048
#define GEMM_SMEM 66560

// grid.x = M_MODELS*MAXT (model = bx>>7, mtile = bx&127), grid.y = 4 (n tiles)
__global__ __launch_bounds__(256)
void gemm_scores_kernel() {
    extern __shared__ char smem[];
    const uint32_t sb = smem_u32(smem);

    const int m  = blockIdx.x >> 7;
    const int mt = blockIdx.x & 127;
    const int cnt = g_counts[m];
    if (mt * TM >= cnt) return;
    const int nt = blockIdx.y;
    const int* rowsm = g_rows + m * T_FRAMES;

    const int tid  = threadIdx.x;
    const int wid  = tid >> 5;
    const int lane = tid & 31;
    const int wr = wid >> 2;      // 0..1 : warp row (64 frames)
    const int wc = wid & 3;       // 0..3 : warp col (32 centroids)

    int*   rowidx_s = reinterpret_cast<int*>(smem + SM_ROWIDX);
    float* chalf_s  = reinterpret_cast<float*>(smem + SM_CHALF);
    if (tid < 128) {
        int gr = mt * TM + tid;
        rowidx_s[tid] = rowsm[min(gr, cnt - 1)];
        chalf_s[tid]  = g_chalf[m * K_CLUST + nt * TN + tid];
    }

    // per-thread cp.async plan: 4 A chunks + 4 B chunks of 16B per stage
    const char* aSrc[4]; const char* bSrc[4]; uint32_t dstOff[4];
    #pragma unroll
    for (int j = 0; j < 4; ++j) {
        int q   = tid + 256 * j;        // 0..1023
        int row = q >> 3;               // 0..127
        int c   = q & 7;                // 16B chunk within 128B row
        dstOff[j] = row * 128 + ((c ^ (row & 7)) << 4);
        int frame = rowsm[min(mt * TM + row, cnt - 1)];
        aSrc[j] = reinterpret_cast<const char*>(g_emb_bf + (size_t)frame * E_DIM) + c * 16;
        int crow = m * K_CLUST + nt * TN + row;
        bSrc[j] = reinterpret_cast<const char*>(g_cent_bf + (size_t)crow * E_DIM) + c * 16;
    }

    float acc[4][4][4];
    #pragma unroll
    for (int mi = 0; mi < 4; ++mi)
        #pragma unroll
        for (int n = 0; n < 4; ++n)
            #pragma unroll
            for (int r = 0; r < 4; ++r) acc[mi][n][r] = 0.f;

    // ldmatrix lane address components
    const int arow_l = wr * 64 + (lane & 7) + ((lane >> 3) & 1) * 8;
    const int brow_l = wc * 32 + (lane & 7) + ((lane >> 3) & 1) * 8;
    const int clane  = lane >> 4;

    // prologue: stage 0
    #pragma unroll
    for (int j = 0; j < 4; ++j) {
        cp16(sb + dstOff[j], aSrc[j]);
        cp16(sb + SM_B0 + dstOff[j], bSrc[j]);
    }
    cp_commit();

    for (int kb = 0; kb < NSTAGE; ++kb) {
        if (kb + 1 < NSTAGE) {
            uint32_t ab = sb + ((kb + 1) & 1) * 16384;
            uint32_t bb = sb + SM_B0 + ((kb + 1) & 1) * 16384;
            int off = (kb + 1) * 128;
            #pragma unroll
            for (int j = 0; j < 4; ++j) {
                cp16(ab + dstOff[j], aSrc[j] + off);
                cp16(bb + dstOff[j], bSrc[j] + off);
            }
            cp_commit();
            asm volatile("cp.async.wait_group 1;" ::: "memory");
        } else {
            asm volatile("cp.async.wait_group 0;" ::: "memory");
        }
        __syncthreads();

        const uint32_t Ab = sb + (kb & 1) * 16384;
        const uint32_t Bb = sb + SM_B0 + (kb & 1) * 16384;
        #pragma unroll
        for (int ks = 0; ks < 4; ++ks) {
            const int cc = ks * 2 + clane;
            uint32_t a[4][4];
            #pragma unroll
            for (int mi = 0; mi < 4; ++mi) {
                int row = arow_l + mi * 16;
                ldmx4(Ab + row * 128 + ((cc ^ (row & 7)) << 4),
                      a[mi][0], a[mi][1], a[mi][2], a[mi][3]);
            }
            uint32_t b[2][4];
            #pragma unroll
            for (int nj = 0; nj < 2; ++nj) {
                int row = brow_l + nj * 16;
                ldmx4(Bb + row * 128 + ((cc ^ (row & 7)) << 4),
                      b[nj][0], b[nj][1], b[nj][2], b[nj][3]);
            }
            #pragma unroll
            for (int mi = 0; mi < 4; ++mi)
                #pragma unroll
                for (int n = 0; n < 4; ++n)
                    mma_bf16(acc[mi][n],
                             a[mi][0], a[mi][1], a[mi][2], a[mi][3],
                             b[n >> 1][n & 1], b[n >> 1][2 + (n & 1)]);
        }
        __syncthreads();
    }

    // epilogue: s = 0.5*c^2 - dot  -> g_scores[frame][ncol]
    const int gid = lane >> 2, tig = lane & 3;
    #pragma unroll
    for (int mi = 0; mi < 4; ++mi) {
        int r0 = wr * 64 + mi * 16 + gid;
        int r1 = r0 + 8;
        int f0 = rowidx_s[r0], f1 = rowidx_s[r1];
        bool v0 = (mt * TM + r0) < cnt;
        bool v1 = (mt * TM + r1) < cnt;
        #pragma unroll
        for (int n = 0; n < 4; ++n) {
            int col = wc * 32 + n * 8 + tig * 2;
            float ch0 = chalf_s[col], ch1 = chalf_s[col + 1];
            if (v0) {
                float2 s0 = make_float2(ch0 - acc[mi][n][0], ch1 - acc[mi][n][1]);
                *reinterpret_cast<float2*>(&g_scores[(size_t)f0 * K_CLUST + nt * TN + col]) = s0;
            }
            if (v1) {
                float2 s1 = make_float2(ch0 - acc[mi][n][2], ch1 - acc[mi][n][3]);
                *reinterpret_cast<float2*>(&g_scores[(size_t)f1 * K_CLUST + nt * TN + col]) = s1;
            }
        }
    }
}

// ================= exact rescoring (one warp per frame) =================
__global__ __launch_bounds__(256)
void rescore_kernel(const float* __restrict__ emb, const float* __restrict__ cent,
                    const int* __restrict__ model_idx) {
    int frame = (blockIdx.x * blockDim.x + threadIdx.x) >> 5;
    int lane  = threadIdx.x & 31;
    if (frame >= T_FRAMES) return;
    int m = model_idx[frame];

    // load this frame's 512 approx scores (lane-strided)
    float sv[16];
    const float* srow = g_scores + (size_t)frame * K_CLUST;
    #pragma unroll
    for (int i = 0; i < 16; ++i) sv[i] = srow[i * 32 + lane];
    float mn = sv[0];
    #pragma unroll
    for (int i = 1; i < 16; ++i) mn = fminf(mn, sv[i]);
    #pragma unroll
    for (int o = 16; o; o >>= 1) mn = fminf(mn, __shfl_xor_sync(0xffffffffu, mn, o));
    const float thr = mn + TAU;

    // cache emb row in registers
    float e[32];
    const float* erow = emb + (size_t)frame * E_DIM;
    #pragma unroll
    for (int j = 0; j < 32; ++j) e[j] = erow[j * 32 + lane];

    float best = __int_as_float(0x7F800000);
    int bk = 0;
    for (int i = 0; i < 16; ++i) {
        unsigned mask = __ballot_sync(0xffffffffu, sv[i] <= thr);
        while (mask) {
            int b = __ffs(mask) - 1;
            mask &= mask - 1;
            int k = i * 32 + b;                       // ascending k order
            const float* crow = cent + (size_t)(m * K_CLUST + k) * E_DIM;
            float d = 0.f;
            #pragma unroll
            for (int j = 0; j < 32; ++j) d += e[j] * crow[j * 32 + lane];
            #pragma unroll
            for (int o = 16; o; o >>= 1) d += __shfl_xor_sync(0xffffffffu, d, o);
            float s = g_chalf[m * K_CLUST + k] - d;   // exact fp32 score
            if (s < best) { best = s; bk = k; }       // strict < : first-min tie-break
        }
    }
    if (lane == 0) g_code[frame] = bk;
}

// ================= output gather =================
__global__ void gather_kernel(const float* __restrict__ cent,
                              const int* __restrict__ model_idx,
                              float* __restrict__ out) {
    int idx = blockIdx.x * blockDim.x + threadIdx.x;   // float4 index
    if (idx >= T_FRAMES * (E_DIM / 4)) return;
    int t  = idx >> 8;
    int e4 = idx & 255;
    int code = g_code[t];
    size_t row = (size_t)(model_idx[t] * K_CLUST + code);
    reinterpret_cast<float4*>(out)[idx] =
        reinterpret_cast<const float4*>(cent)[row * 256 + e4];
}

// ================= launch =================
extern "C" void kernel_launch(void* const* d_in, const int* in_sizes, int n_in,
                              void* d_out, int out_size) {
    const float* emb  = (const float*)d_in[0];
    const float* cent = (const float*)d_in[1];
    const int*   midx = (const int*)d_in[2];
    float* out = (float*)d_out;

    cudaFuncSetAttribute(gemm_scores_kernel,
                         cudaFuncAttributeMaxDynamicSharedMemorySize, GEMM_SMEM);

    init_kernel<<<1, 32>>>();
    bucket_kernel<<<(T_FRAMES + 255) / 256, 256>>>(midx);
    cvt_emb_kernel<<<(T_FRAMES * E_DIM / 4 + 255) / 256, 256>>>(emb);
    cvt_cent_kernel<<<(M_MODELS * K_CLUST * E_DIM / 4 + 255) / 256, 256>>>(cent);
    chalf_kernel<<<(M_MODELS * K_CLUST * 32 + 255) / 256, 256>>>(cent);

    dim3 grid(M_MODELS * MAXT, K_CLUST / TN);   // (1024, 4), empty tiles exit early
    gemm_scores_kernel<<<grid, 256, GEMM_SMEM>>>();

    rescore_kernel<<<(T_FRAMES * 32 + 255) / 256, 256>>>(emb, cent, midx);
    gather_kernel<<<(T_FRAMES * (E_DIM / 4) + 255) / 256, 256>>>(cent, midx, out);
}

// round 6
// speedup vs baseline: 2.5048x; 1.0108x over previous
#include <cuda_runtime.h>
#include <cuda_bf16.h>
#include <cstdint>

#define T_FRAMES 16384
#define E_DIM    1024
#define M_MODELS 8
#define K_CLUST  512

#define TM   64             // frames per CTA
#define TN   512            // all centroids of the model
#define KBLK 64             // bf16 K elements per stage (128B rows)
#define NSTAGE (E_DIM / KBLK)   // 16
#define MAXT (T_FRAMES / TM)    // 256
#define NTHREADS 512
#define TAU  10.0f
#define CAP  6144           // candidate list capacity (stat bound ~115/CTA)

// ---- persistent scratch ----
__device__ __nv_bfloat16 g_cent_bf[M_MODELS * K_CLUST * E_DIM];   // 8.4MB
__device__ int   g_counts[M_MODELS];
__device__ int   g_rows[M_MODELS * T_FRAMES];
__device__ float g_chalf[M_MODELS * K_CLUST];

// ================= helpers =================
__device__ __forceinline__ uint32_t smem_u32(const void* p) {
    uint32_t a;
    asm("{ .reg .u64 t; cvta.to.shared.u64 t, %1; cvt.u32.u64 %0, t; }" : "=r"(a) : "l"(p));
    return a;
}
__device__ __forceinline__ void cp16(uint32_t dst, const void* src) {
    asm volatile("cp.async.cg.shared.global [%0], [%1], 16;" :: "r"(dst), "l"(src));
}
__device__ __forceinline__ void ldmx4(uint32_t addr, uint32_t& r0, uint32_t& r1,
                                      uint32_t& r2, uint32_t& r3) {
    asm volatile("ldmatrix.sync.aligned.m8n8.x4.shared.b16 {%0,%1,%2,%3}, [%4];"
                 : "=r"(r0), "=r"(r1), "=r"(r2), "=r"(r3) : "r"(addr));
}
__device__ __forceinline__ void mma_bf16(float* c, uint32_t a0, uint32_t a1,
                                         uint32_t a2, uint32_t a3,
                                         uint32_t b0, uint32_t b1) {
    asm volatile(
        "mma.sync.aligned.m16n8k16.row.col.f32.bf16.bf16.f32 "
        "{%0,%1,%2,%3}, {%4,%5,%6,%7}, {%8,%9}, {%0,%1,%2,%3};"
        : "+f"(c[0]), "+f"(c[1]), "+f"(c[2]), "+f"(c[3])
        : "r"(a0), "r"(a1), "r"(a2), "r"(a3), "r"(b0), "r"(b1));
}
__device__ __forceinline__ unsigned int fkey(float f) {
    unsigned u = __float_as_uint(f);
    return (u & 0x80000000u) ? ~u : (u | 0x80000000u);
}
__device__ __forceinline__ uint2 f4_to_bf8(float4 v) {
    __nv_bfloat162 p0 = __floats2bfloat162_rn(v.x, v.y);
    __nv_bfloat162 p1 = __floats2bfloat162_rn(v.z, v.w);
    uint2 r;
    r.x = *reinterpret_cast<uint32_t*>(&p0);
    r.y = *reinterpret_cast<uint32_t*>(&p1);
    return r;
}

// ================= smem layout (bytes) =================
#define SM_B      0                       // 2 x 64KB
#define SM_A      131072                  // 2 x 8KB
#define SM_CHALF  147456                  // 512 f32
#define SM_ROWIDX 149504                  // 64 int
#define SM_THR    149760                  // 64 f32
#define SM_PMIN   150016                  // 64 x 8 f32
#define SM_BEST   152064                  // 64 u64
#define SM_CNT    152576                  // int
#define SM_CODE   152580                  // 64 int
#define SM_CAND   152836                  // CAP ints
#define SMEM_TOTAL (152836 + CAP * 4 + 64)

// ================= prep kernels =================
__global__ void init_kernel() {
    int t = threadIdx.x;
    if (t < M_MODELS) g_counts[t] = 0;
}

__global__ void bucket_kernel(const int* __restrict__ model_idx) {
    int t = blockIdx.x * blockDim.x + threadIdx.x;
    if (t >= T_FRAMES) return;
    int m = model_idx[t];
    int pos = atomicAdd(&g_counts[m], 1);
    g_rows[m * T_FRAMES + pos] = t;
}

// one warp per centroid row: convert f32->bf16 AND compute 0.5*|c|^2 in one read
__global__ void prep_cent_kernel(const float* __restrict__ cent) {
    int warp = (blockIdx.x * blockDim.x + threadIdx.x) >> 5;
    int lane = threadIdx.x & 31;
    if (warp >= M_MODELS * K_CLUST) return;
    const float4* src = reinterpret_cast<const float4*>(cent + (size_t)warp * E_DIM);
    uint2* dst = reinterpret_cast<uint2*>(g_cent_bf + (size_t)warp * E_DIM);
    float s = 0.f;
    #pragma unroll
    for (int q = 0; q < 8; ++q) {
        float4 v = src[lane + 32 * q];
        dst[lane + 32 * q] = f4_to_bf8(v);
        s += v.x * v.x + v.y * v.y + v.z * v.z + v.w * v.w;
    }
    #pragma unroll
    for (int o = 16; o; o >>= 1) s += __shfl_xor_sync(0xffffffffu, s, o);
    if (lane == 0) g_chalf[warp] = 0.5f * s;
}

// ================= fused GEMM + argmin + rescore + output =================
// grid.x = M_MODELS * MAXT : m = bx>>8, mt = bx&255
__global__ __launch_bounds__(NTHREADS, 1)
void fused_kernel(const float* __restrict__ emb, const float* __restrict__ cent,
                  float* __restrict__ out) {
    extern __shared__ char smem[];
    const uint32_t sb = smem_u32(smem);

    const int m  = blockIdx.x >> 8;
    const int mt = blockIdx.x & 255;
    const int cnt = g_counts[m];
    if (mt * TM >= cnt) return;
    const int* rowsm = g_rows + m * T_FRAMES;

    const int tid  = threadIdx.x;
    const int wid  = tid >> 5;
    const int lane = tid & 31;
    const int wr = wid >> 3;      // 0..1  : 32-frame rows
    const int wc = wid & 7;       // 0..7  : 64-centroid cols

    int*   rowidx_s = reinterpret_cast<int*>(smem + SM_ROWIDX);
    float* chalf_s  = reinterpret_cast<float*>(smem + SM_CHALF);
    float* thr_s    = reinterpret_cast<float*>(smem + SM_THR);
    float* pmin_s   = reinterpret_cast<float*>(smem + SM_PMIN);
    unsigned long long* best_s = reinterpret_cast<unsigned long long*>(smem + SM_BEST);
    int* cnt_s  = reinterpret_cast<int*>(smem + SM_CNT);
    int* code_s = reinterpret_cast<int*>(smem + SM_CODE);
    int* cand_s = reinterpret_cast<int*>(smem + SM_CAND);

    if (tid < TM) {
        int gr = mt * TM + tid;
        rowidx_s[tid] = rowsm[min(gr, cnt - 1)];
        best_s[tid] = 0xFFFFFFFFFFFFFFFFull;
    }
    chalf_s[tid] = g_chalf[m * K_CLUST + tid];
    if (tid == 0) cnt_s[0] = 0;
    __syncthreads();

    // ---- A producer plan: 2 float4/thread/stage (64 rows x 16 float4) ----
    const int ar0 = tid >> 4,          af0 = tid & 15;
    const int ar1 = (tid + 512) >> 4,  af1 = (tid + 512) & 15;
    const float4* aS0 = reinterpret_cast<const float4*>(emb + (size_t)rowidx_s[ar0] * E_DIM) + af0;
    const float4* aS1 = reinterpret_cast<const float4*>(emb + (size_t)rowidx_s[ar1] * E_DIM) + af1;
    const uint32_t ad0 = ar0 * 128 + (((af0 >> 1) ^ (ar0 & 7)) << 4) + (af0 & 1) * 8;
    const uint32_t ad1 = ar1 * 128 + (((af1 >> 1) ^ (ar1 & 7)) << 4) + (af1 & 1) * 8;

    // ---- B producer plan: one row per thread, 8 x 16B chunks/stage ----
    const char* bS = reinterpret_cast<const char*>(g_cent_bf + ((size_t)m * K_CLUST + tid) * E_DIM);
    uint32_t bd[8];
    #pragma unroll
    for (int c = 0; c < 8; ++c) bd[c] = tid * 128 + ((c ^ (tid & 7)) << 4);

    float acc[2][8][4];
    #pragma unroll
    for (int mi = 0; mi < 2; ++mi)
        #pragma unroll
        for (int n = 0; n < 8; ++n)
            #pragma unroll
            for (int r = 0; r < 4; ++r) acc[mi][n][r] = 0.f;

    const int arow_l = wr * 32 + (lane & 7) + ((lane >> 3) & 1) * 8;
    const int brow_l = wc * 64 + (lane & 7) + ((lane >> 3) & 1) * 8;
    const int clane  = lane >> 4;

    // prologue: A0 regs + B0 async
    float4 apre0 = aS0[0], apre1 = aS1[0];
    #pragma unroll
    for (int c = 0; c < 8; ++c) cp16(sb + SM_B + bd[c], bS + c * 16);
    asm volatile("cp.async.commit_group;" ::: "memory");

    for (int kb = 0; kb < NSTAGE; ++kb) {
        const uint32_t Ab = sb + SM_A + (kb & 1) * 8192;
        const uint32_t Bb = sb + SM_B + (kb & 1) * 65536;
        // store current A stage
        *reinterpret_cast<uint2*>(smem + SM_A + (kb & 1) * 8192 + ad0) = f4_to_bf8(apre0);
        *reinterpret_cast<uint2*>(smem + SM_A + (kb & 1) * 8192 + ad1) = f4_to_bf8(apre1);
        // prefetch next stage
        if (kb + 1 < NSTAGE) {
            uint32_t Bn = sb + SM_B + ((kb + 1) & 1) * 65536;
            #pragma unroll
            for (int c = 0; c < 8; ++c) cp16(Bn + bd[c], bS + (kb + 1) * 128 + c * 16);
            asm volatile("cp.async.commit_group;" ::: "memory");
            apre0 = aS0[(kb + 1) * 16];
            apre1 = aS1[(kb + 1) * 16];
            asm volatile("cp.async.wait_group 1;" ::: "memory");
        } else {
            asm volatile("cp.async.wait_group 0;" ::: "memory");
        }
        __syncthreads();

        #pragma unroll
        for (int ks = 0; ks < 4; ++ks) {
            const int cc = ks * 2 + clane;
            uint32_t a[2][4];
            #pragma unroll
            for (int mi = 0; mi < 2; ++mi) {
                int row = arow_l + mi * 16;
                ldmx4(Ab + row * 128 + ((cc ^ (row & 7)) << 4),
                      a[mi][0], a[mi][1], a[mi][2], a[mi][3]);
            }
            uint32_t b[4][4];
            #pragma unroll
            for (int nj = 0; nj < 4; ++nj) {
                int row = brow_l + nj * 16;
                ldmx4(Bb + row * 128 + ((cc ^ (row & 7)) << 4),
                      b[nj][0], b[nj][1], b[nj][2], b[nj][3]);
            }
            #pragma unroll
            for (int mi = 0; mi < 2; ++mi)
                #pragma unroll
                for (int n = 0; n < 8; ++n)
                    mma_bf16(acc[mi][n],
                             a[mi][0], a[mi][1], a[mi][2], a[mi][3],
                             b[n >> 1][n & 1], b[n >> 1][2 + (n & 1)]);
        }
        __syncthreads();
    }

    // ---- epilogue 1: per-row approx min over this warp's 64 cols ----
    const int gid = lane >> 2, tig = lane & 3;
    #pragma unroll
    for (int mi = 0; mi < 2; ++mi) {
        float v0 = __int_as_float(0x7F800000), v1 = v0;
        #pragma unroll
        for (int n = 0; n < 8; ++n) {
            int col = wc * 64 + n * 8 + tig * 2;
            float c0 = chalf_s[col], c1 = chalf_s[col + 1];
            v0 = fminf(v0, fminf(c0 - acc[mi][n][0], c1 - acc[mi][n][1]));
            v1 = fminf(v1, fminf(c0 - acc[mi][n][2], c1 - acc[mi][n][3]));
        }
        #pragma unroll
        for (int o = 1; o < 4; o <<= 1) {
            v0 = fminf(v0, __shfl_xor_sync(0xffffffffu, v0, o));
            v1 = fminf(v1, __shfl_xor_sync(0xffffffffu, v1, o));
        }
        if (tig == 0) {
            pmin_s[(wr * 32 + mi * 16 + gid) * 8 + wc] = v0;
            pmin_s[(wr * 32 + mi * 16 + gid + 8) * 8 + wc] = v1;
        }
    }
    __syncthreads();
    if (tid < TM) {
        float v = pmin_s[tid * 8];
        #pragma unroll
        for (int w = 1; w < 8; ++w) v = fminf(v, pmin_s[tid * 8 + w]);
        thr_s[tid] = v + TAU;
    }
    __syncthreads();

    // ---- epilogue 2: collect candidates ----
    #pragma unroll
    for (int mi = 0; mi < 2; ++mi) {
        #pragma unroll
        for (int n = 0; n < 8; ++n) {
            #pragma unroll
            for (int r = 0; r < 4; ++r) {
                int row = wr * 32 + mi * 16 + gid + (r >> 1) * 8;
                int col = wc * 64 + n * 8 + tig * 2 + (r & 1);
                float s = chalf_s[col] - acc[mi][n][r];
                if (s <= thr_s[row]) {
                    int idx = atomicAdd(cnt_s, 1);
                    if (idx < CAP) cand_s[idx] = (row << 16) | col;
                }
            }
        }
    }
    __syncthreads();
    const int ncand = min(cnt_s[0], CAP);

    // ---- epilogue 3: exact fp32 rescoring of candidates (one warp each) ----
    const float4* emb4  = reinterpret_cast<const float4*>(emb);
    const float4* cent4 = reinterpret_cast<const float4*>(cent);
    for (int i = wid; i < ncand; i += 16) {
        int rc = cand_s[i];
        int row = rc >> 16, col = rc & 0xFFFF;
        const float4* e4 = emb4 + (size_t)rowidx_s[row] * 256;
        const float4* c4 = cent4 + ((size_t)m * K_CLUST + col) * 256;
        float d = 0.f;
        #pragma unroll
        for (int q = 0; q < 8; ++q) {
            float4 ea = e4[q * 32 + lane];
            float4 ca = c4[q * 32 + lane];
            d += ea.x * ca.x + ea.y * ca.y + ea.z * ca.z + ea.w * ca.w;
        }
        #pragma unroll
        for (int o = 16; o; o >>= 1) d += __shfl_xor_sync(0xffffffffu, d, o);
        if (lane == 0) {
            float s = chalf_s[col] - d;   // exact fp32 score
            unsigned long long key = ((unsigned long long)fkey(s) << 32) | (unsigned)col;
            atomicMin(&best_s[row], key); // ties -> smaller col (first-min semantics)
        }
    }
    __syncthreads();
    if (tid < TM) code_s[tid] = (int)(unsigned)(best_s[tid] & 0xFFFFFFFFull);
    __syncthreads();

    // ---- epilogue 4: write output rows directly ----
    float4* out4 = reinterpret_cast<float4*>(out);
    for (int idx = tid; idx < TM * 256; idx += NTHREADS) {
        int r = idx >> 8, q = idx & 255;
        if (mt * TM + r < cnt) {
            int frame = rowidx_s[r];
            out4[(size_t)frame * 256 + q] =
                cent4[((size_t)m * K_CLUST + code_s[r]) * 256 + q];
        }
    }
}

// ================= launch =================
extern "C" void kernel_launch(void* const* d_in, const int* in_sizes, int n_in,
                              void* d_out, int out_size) {
    const float* emb  = (const float*)d_in[0];
    const float* cent = (const float*)d_in[1];
    const int*   midx = (const int*)d_in[2];
    float* out = (float*)d_out;

    cudaFuncSetAttribute(fused_kernel,
                         cudaFuncAttributeMaxDynamicSharedMemorySize, SMEM_TOTAL);

    init_kernel<<<1, 32>>>();
    bucket_kernel<<<(T_FRAMES + 255) / 256, 256>>>(midx);
    prep_cent_kernel<<<(M_MODELS * K_CLUST * 32 + 255) / 256, 256>>>(cent);

    fused_kernel<<<M_MODELS * MAXT, NTHREADS, SMEM_TOTAL>>>(emb, cent, out);
}

// round 7
// speedup vs baseline: 2.9034x; 1.1591x over previous
#include <cuda_runtime.h>
#include <cuda_bf16.h>
#include <cstdint>

#define T_FRAMES 16384
#define E_DIM    1024
#define M_MODELS 8
#define K_CLUST  512

#define TM   64             // frames per CTA
#define TN   512            // all centroids of the model
#define KBLK 64             // bf16 K elements per stage (128B rows)
#define NSTAGE (E_DIM / KBLK)   // 16
#define MAXT (T_FRAMES / TM)    // 256
#define NTHREADS 1024
#define TAU  10.0f
#define CAP  6144

// ---- persistent scratch ----
__device__ __nv_bfloat16 g_cent_bf[M_MODELS * K_CLUST * E_DIM];   // 8.4MB
__device__ int   g_counts[M_MODELS];
__device__ int   g_rows[M_MODELS * T_FRAMES];
__device__ float g_chalf[M_MODELS * K_CLUST];

// ================= helpers =================
__device__ __forceinline__ uint32_t smem_u32(const void* p) {
    uint32_t a;
    asm("{ .reg .u64 t; cvta.to.shared.u64 t, %1; cvt.u32.u64 %0, t; }" : "=r"(a) : "l"(p));
    return a;
}
__device__ __forceinline__ void cp16(uint32_t dst, const void* src) {
    asm volatile("cp.async.cg.shared.global [%0], [%1], 16;" :: "r"(dst), "l"(src));
}
__device__ __forceinline__ void ldmx4(uint32_t addr, uint32_t& r0, uint32_t& r1,
                                      uint32_t& r2, uint32_t& r3) {
    asm volatile("ldmatrix.sync.aligned.m8n8.x4.shared.b16 {%0,%1,%2,%3}, [%4];"
                 : "=r"(r0), "=r"(r1), "=r"(r2), "=r"(r3) : "r"(addr));
}
__device__ __forceinline__ void mma_bf16(float* c, uint32_t a0, uint32_t a1,
                                         uint32_t a2, uint32_t a3,
                                         uint32_t b0, uint32_t b1) {
    asm volatile(
        "mma.sync.aligned.m16n8k16.row.col.f32.bf16.bf16.f32 "
        "{%0,%1,%2,%3}, {%4,%5,%6,%7}, {%8,%9}, {%0,%1,%2,%3};"
        : "+f"(c[0]), "+f"(c[1]), "+f"(c[2]), "+f"(c[3])
        : "r"(a0), "r"(a1), "r"(a2), "r"(a3), "r"(b0), "r"(b1));
}
__device__ __forceinline__ unsigned int fkey(float f) {
    unsigned u = __float_as_uint(f);
    return (u & 0x80000000u) ? ~u : (u | 0x80000000u);
}
__device__ __forceinline__ uint2 f4_to_bf8(float4 v) {
    __nv_bfloat162 p0 = __floats2bfloat162_rn(v.x, v.y);
    __nv_bfloat162 p1 = __floats2bfloat162_rn(v.z, v.w);
    uint2 r;
    r.x = *reinterpret_cast<uint32_t*>(&p0);
    r.y = *reinterpret_cast<uint32_t*>(&p1);
    return r;
}

// ================= smem layout (bytes) =================
#define SM_B      0                       // 2 x 64KB
#define SM_A      131072                  // 2 x 8KB
#define SM_CHALF  147456                  // 512 f32
#define SM_ROWIDX 149504                  // 64 int
#define SM_THR    149760                  // 64 f32
#define SM_PMIN   150016                  // 64 x 8 f32
#define SM_BEST   152064                  // 64 u64
#define SM_CNT    152576                  // int
#define SM_CODE   152580                  // 64 int
#define SM_CAND   152836                  // CAP ints
#define SMEM_TOTAL (152836 + CAP * 4 + 64)

// ================= prep kernels =================
__global__ void init_kernel() {
    int t = threadIdx.x;
    if (t < M_MODELS) g_counts[t] = 0;
}

__global__ void bucket_kernel(const int* __restrict__ model_idx) {
    int t = blockIdx.x * blockDim.x + threadIdx.x;
    if (t >= T_FRAMES) return;
    int m = model_idx[t];
    int pos = atomicAdd(&g_counts[m], 1);
    g_rows[m * T_FRAMES + pos] = t;
}

// one warp per centroid row: convert f32->bf16 AND compute 0.5*|c|^2 in one read
__global__ void prep_cent_kernel(const float* __restrict__ cent) {
    int warp = (blockIdx.x * blockDim.x + threadIdx.x) >> 5;
    int lane = threadIdx.x & 31;
    if (warp >= M_MODELS * K_CLUST) return;
    const float4* src = reinterpret_cast<const float4*>(cent + (size_t)warp * E_DIM);
    uint2* dst = reinterpret_cast<uint2*>(g_cent_bf + (size_t)warp * E_DIM);
    float s = 0.f;
    #pragma unroll
    for (int q = 0; q < 8; ++q) {
        float4 v = src[lane + 32 * q];
        dst[lane + 32 * q] = f4_to_bf8(v);
        s += v.x * v.x + v.y * v.y + v.z * v.z + v.w * v.w;
    }
    #pragma unroll
    for (int o = 16; o; o >>= 1) s += __shfl_xor_sync(0xffffffffu, s, o);
    if (lane == 0) g_chalf[warp] = 0.5f * s;
}

// ================= fused GEMM + argmin + rescore + output =================
// grid.x = M_MODELS * MAXT : m = bx>>8, mt = bx&255
__global__ __launch_bounds__(NTHREADS, 1)
void fused_kernel(const float* __restrict__ emb, const float* __restrict__ cent,
                  float* __restrict__ out) {
    extern __shared__ char smem[];
    const uint32_t sb = smem_u32(smem);

    const int m  = blockIdx.x >> 8;
    const int mt = blockIdx.x & 255;
    const int cnt = g_counts[m];
    if (mt * TM >= cnt) return;
    const int* rowsm = g_rows + m * T_FRAMES;

    const int tid  = threadIdx.x;
    const int wid  = tid >> 5;
    const int lane = tid & 31;
    const int wr = wid >> 3;      // 0..3 : 16-frame row group
    const int wc = wid & 7;       // 0..7 : 64-centroid col group

    int*   rowidx_s = reinterpret_cast<int*>(smem + SM_ROWIDX);
    float* chalf_s  = reinterpret_cast<float*>(smem + SM_CHALF);
    float* thr_s    = reinterpret_cast<float*>(smem + SM_THR);
    float* pmin_s   = reinterpret_cast<float*>(smem + SM_PMIN);
    unsigned long long* best_s = reinterpret_cast<unsigned long long*>(smem + SM_BEST);
    int* cnt_s  = reinterpret_cast<int*>(smem + SM_CNT);
    int* code_s = reinterpret_cast<int*>(smem + SM_CODE);
    int* cand_s = reinterpret_cast<int*>(smem + SM_CAND);

    if (tid < TM) {
        int gr = mt * TM + tid;
        rowidx_s[tid] = rowsm[min(gr, cnt - 1)];
        best_s[tid] = 0xFFFFFFFFFFFFFFFFull;
    }
    if (tid < TN) chalf_s[tid] = g_chalf[m * K_CLUST + tid];
    if (tid == 0) cnt_s[0] = 0;
    __syncthreads();

    // ---- A producer plan: 1 float4/thread/stage (64 rows x 16 float4) ----
    const int ar = tid >> 4, af = tid & 15;
    const float4* aS = reinterpret_cast<const float4*>(emb + (size_t)rowidx_s[ar] * E_DIM) + af;
    const uint32_t ad = ar * 128 + (((af >> 1) ^ (ar & 7)) << 4) + (af & 1) * 8;

    // ---- B producer plan: half-row per thread (4 x 16B chunks/stage) ----
    const int brow = tid >> 1, bh = tid & 1;
    const char* bS = reinterpret_cast<const char*>(
        g_cent_bf + ((size_t)m * K_CLUST + brow) * E_DIM) + bh * 64;
    uint32_t bd[4];
    #pragma unroll
    for (int c = 0; c < 4; ++c)
        bd[c] = brow * 128 + (((bh * 4 + c) ^ (brow & 7)) << 4);

    float acc[8][4];
    #pragma unroll
    for (int n = 0; n < 8; ++n)
        #pragma unroll
        for (int r = 0; r < 4; ++r) acc[n][r] = 0.f;

    const int arow_l = wr * 16 + (lane & 7) + ((lane >> 3) & 1) * 8;
    const int brow_l = wc * 64 + (lane & 7) + ((lane >> 3) & 1) * 8;
    const int clane  = lane >> 4;

    // prologue
    float4 apre = aS[0];
    #pragma unroll
    for (int c = 0; c < 4; ++c) cp16(sb + SM_B + bd[c], bS + c * 16);
    asm volatile("cp.async.commit_group;" ::: "memory");

    for (int kb = 0; kb < NSTAGE; ++kb) {
        const uint32_t Ab = sb + SM_A + (kb & 1) * 8192;
        const uint32_t Bb = sb + SM_B + (kb & 1) * 65536;
        *reinterpret_cast<uint2*>(smem + SM_A + (kb & 1) * 8192 + ad) = f4_to_bf8(apre);
        if (kb + 1 < NSTAGE) {
            uint32_t Bn = sb + SM_B + ((kb + 1) & 1) * 65536;
            #pragma unroll
            for (int c = 0; c < 4; ++c) cp16(Bn + bd[c], bS + (kb + 1) * 128 + c * 16);
            asm volatile("cp.async.commit_group;" ::: "memory");
            apre = aS[(kb + 1) * 16];
            asm volatile("cp.async.wait_group 1;" ::: "memory");
        } else {
            asm volatile("cp.async.wait_group 0;" ::: "memory");
        }
        __syncthreads();

        #pragma unroll
        for (int ks = 0; ks < 4; ++ks) {
            const int cc = ks * 2 + clane;
            uint32_t a0, a1, a2, a3;
            ldmx4(Ab + arow_l * 128 + ((cc ^ (arow_l & 7)) << 4), a0, a1, a2, a3);
            #pragma unroll
            for (int nh = 0; nh < 2; ++nh) {
                uint32_t b[2][4];
                #pragma unroll
                for (int nj = 0; nj < 2; ++nj) {
                    int row = brow_l + nh * 32 + nj * 16;
                    ldmx4(Bb + row * 128 + ((cc ^ (row & 7)) << 4),
                          b[nj][0], b[nj][1], b[nj][2], b[nj][3]);
                }
                #pragma unroll
                for (int n = 0; n < 4; ++n)
                    mma_bf16(acc[nh * 4 + n], a0, a1, a2, a3,
                             b[n >> 1][n & 1], b[n >> 1][2 + (n & 1)]);
            }
        }
        __syncthreads();
    }

    // ---- epilogue 1: per-row approx min over this warp's 64 cols ----
    const int gid = lane >> 2, tig = lane & 3;
    {
        float v0 = __int_as_float(0x7F800000), v1 = v0;
        #pragma unroll
        for (int n = 0; n < 8; ++n) {
            int col = wc * 64 + n * 8 + tig * 2;
            float c0 = chalf_s[col], c1 = chalf_s[col + 1];
            v0 = fminf(v0, fminf(c0 - acc[n][0], c1 - acc[n][1]));
            v1 = fminf(v1, fminf(c0 - acc[n][2], c1 - acc[n][3]));
        }
        #pragma unroll
        for (int o = 1; o < 4; o <<= 1) {
            v0 = fminf(v0, __shfl_xor_sync(0xffffffffu, v0, o));
            v1 = fminf(v1, __shfl_xor_sync(0xffffffffu, v1, o));
        }
        if (tig == 0) {
            pmin_s[(wr * 16 + gid) * 8 + wc] = v0;
            pmin_s[(wr * 16 + gid + 8) * 8 + wc] = v1;
        }
    }
    __syncthreads();
    if (tid < TM) {
        float v = pmin_s[tid * 8];
        #pragma unroll
        for (int w = 1; w < 8; ++w) v = fminf(v, pmin_s[tid * 8 + w]);
        thr_s[tid] = v + TAU;
    }
    __syncthreads();

    // ---- epilogue 2: collect candidates ----
    #pragma unroll
    for (int n = 0; n < 8; ++n) {
        #pragma unroll
        for (int r = 0; r < 4; ++r) {
            int row = wr * 16 + gid + (r >> 1) * 8;
            int col = wc * 64 + n * 8 + tig * 2 + (r & 1);
            float s = chalf_s[col] - acc[n][r];
            if (s <= thr_s[row]) {
                int idx = atomicAdd(cnt_s, 1);
                if (idx < CAP) cand_s[idx] = (row << 16) | col;
            }
        }
    }
    __syncthreads();
    const int ncand = min(cnt_s[0], CAP);

    // ---- epilogue 3: exact fp32 rescoring of candidates (one warp each) ----
    const float4* emb4  = reinterpret_cast<const float4*>(emb);
    const float4* cent4 = reinterpret_cast<const float4*>(cent);
    for (int i = wid; i < ncand; i += 32) {
        int rc = cand_s[i];
        int row = rc >> 16, col = rc & 0xFFFF;
        const float4* e4 = emb4 + (size_t)rowidx_s[row] * 256;
        const float4* c4 = cent4 + ((size_t)m * K_CLUST + col) * 256;
        float d = 0.f;
        #pragma unroll
        for (int q = 0; q < 8; ++q) {
            float4 ea = e4[q * 32 + lane];
            float4 ca = c4[q * 32 + lane];
            d += ea.x * ca.x + ea.y * ca.y + ea.z * ca.z + ea.w * ca.w;
        }
        #pragma unroll
        for (int o = 16; o; o >>= 1) d += __shfl_xor_sync(0xffffffffu, d, o);
        if (lane == 0) {
            float s = chalf_s[col] - d;   // exact fp32 score
            unsigned long long key = ((unsigned long long)fkey(s) << 32) | (unsigned)col;
            atomicMin(&best_s[row], key); // ties -> smaller col (first-min semantics)
        }
    }
    __syncthreads();
    if (tid < TM) code_s[tid] = (int)(unsigned)(best_s[tid] & 0xFFFFFFFFull);
    __syncthreads();

    // ---- epilogue 4: write output rows directly ----
    float4* out4 = reinterpret_cast<float4*>(out);
    for (int idx = tid; idx < TM * 256; idx += NTHREADS) {
        int r = idx >> 8, q = idx & 255;
        if (mt * TM + r < cnt) {
            int frame = rowidx_s[r];
            out4[(size_t)frame * 256 + q] =
                cent4[((size_t)m * K_CLUST + code_s[r]) * 256 + q];
        }
    }
}

// ================= launch =================
extern "C" void kernel_launch(void* const* d_in, const int* in_sizes, int n_in,
                              void* d_out, int out_size) {
    const float* emb  = (const float*)d_in[0];
    const float* cent = (const float*)d_in[1];
    const int*   midx = (const int*)d_in[2];
    float* out = (float*)d_out;

    cudaFuncSetAttribute(fused_kernel,
                         cudaFuncAttributeMaxDynamicSharedMemorySize, SMEM_TOTAL);

    init_kernel<<<1, 32>>>();
    bucket_kernel<<<(T_FRAMES + 255) / 256, 256>>>(midx);
    prep_cent_kernel<<<(M_MODELS * K_CLUST * 32 + 255) / 256, 256>>>(cent);

    fused_kernel<<<M_MODELS * MAXT, NTHREADS, SMEM_TOTAL>>>(emb, cent, out);
}